// round 1
// baseline (speedup 1.0000x reference)
#include <cuda_runtime.h>

// SpatialGradientLoss3D: mean |sobel3d(pred) - sobel3d(target)| over 3 axes.
// Linear conv => compute sobel of e = pred - target directly.
// Shapes fixed: (B=4, C=4, D=64, H=128, W=128), fp32, out = 1 float.

#define D_DIM 64
#define H_DIM 128
#define W_DIM 128
#define BC_DIM 16            // B*C
#define TW 32                // tile width  (outputs)
#define TH 32                // tile height (outputs)
#define ZC 32                // z-chunk per block
#define WPT 4                // outputs per thread along w
#define STRIDE 35            // smem row stride (conflict-free padding)
#define PLANE_ROWS 34        // TH + 2 halo
#define PLANE_COLS 34        // TW + 2 halo

__device__ __forceinline__ float kINV_N() {
    // 3 gradient channels * B*C*D*H*W voxels
    return 1.0f / (3.0f * 16.0f * 64.0f * 128.0f * 128.0f);
}

__global__ void sg3d_zero_out(float* out) { out[0] = 0.0f; }

// Load one z-plane of diff (with h/w halo, zero padding) into smem.
__device__ __forceinline__ void load_plane(const float* __restrict__ P,
                                           const float* __restrict__ T,
                                           int z, int h0, int w0, int tid,
                                           float* sp) {
#pragma unroll
    for (int k = 0; k < 5; ++k) {
        int idx = tid + k * 256;
        if (idx < PLANE_ROWS * PLANE_COLS) {
            int r = idx / PLANE_COLS;
            int c = idx - r * PLANE_COLS;
            int gh = h0 - 1 + r;
            int gw = w0 - 1 + c;
            float v = 0.0f;
            if ((unsigned)gh < (unsigned)H_DIM && (unsigned)gw < (unsigned)W_DIM) {
                size_t o = ((size_t)z * H_DIM + gh) * W_DIM + gw;
                v = __ldg(P + o) - __ldg(T + o);
            }
            sp[r * STRIDE + c] = v;
        }
    }
}

// Per-plane separable (w then h) partials for this thread's 4 output columns:
//   ss = smooth_h(smooth_w(e))   -> used for d-derivative (z diff)
//   ds = deriv_h (smooth_w(e))   -> used for h gradient (z smooth)
//   sd = smooth_h(deriv_w (e))   -> used for w gradient (z smooth)
__device__ __forceinline__ void compute_A(const float* sp, int hy, int wg,
                                          float* ss, float* ds, float* sd) {
    float rs[3][6];
#pragma unroll
    for (int rr = 0; rr < 3; ++rr) {
        const float* row = sp + (hy + rr) * STRIDE + wg * WPT;
#pragma unroll
        for (int i = 0; i < 6; ++i) rs[rr][i] = row[i];
    }
#pragma unroll
    for (int i = 0; i < WPT; ++i) {
        float as_m = rs[0][i] + 2.0f * rs[0][i + 1] + rs[0][i + 2];
        float as_0 = rs[1][i] + 2.0f * rs[1][i + 1] + rs[1][i + 2];
        float as_p = rs[2][i] + 2.0f * rs[2][i + 1] + rs[2][i + 2];
        float ad_m = rs[0][i + 2] - rs[0][i];
        float ad_0 = rs[1][i + 2] - rs[1][i];
        float ad_p = rs[2][i + 2] - rs[2][i];
        ss[i] = as_m + 2.0f * as_0 + as_p;
        ds[i] = as_p - as_m;
        sd[i] = ad_m + 2.0f * ad_0 + ad_p;
    }
}

__global__ __launch_bounds__(256, 2)
void sg3d_loss_kernel(const float* __restrict__ pred,
                      const float* __restrict__ tgt,
                      float* __restrict__ out) {
    const int wg = threadIdx.x;   // 0..7  (w group of 4)
    const int hy = threadIdx.y;   // 0..31 (h row)
    const int tid = hy * 8 + wg;

    const int w0 = blockIdx.x * TW;
    const int h0 = blockIdx.y * TH;
    const int bc = blockIdx.z >> 1;
    const int z0 = (blockIdx.z & 1) * ZC;

    const size_t base = (size_t)bc * D_DIM * H_DIM * W_DIM;
    const float* P = pred + base;
    const float* T = tgt + base;

    __shared__ float sp[PLANE_ROWS * STRIDE];

    float ss_m1[WPT], ds_m1[WPT], sd_m1[WPT];
    float ss_0[WPT],  ds_0[WPT],  sd_0[WPT];
    float ss_p1[WPT], ds_p1[WPT], sd_p1[WPT];

    // plane z0-1
    if (z0 > 0) {
        load_plane(P, T, z0 - 1, h0, w0, tid, sp);
        __syncthreads();
        compute_A(sp, hy, wg, ss_m1, ds_m1, sd_m1);
        __syncthreads();
    } else {
#pragma unroll
        for (int i = 0; i < WPT; ++i) { ss_m1[i] = 0.f; ds_m1[i] = 0.f; sd_m1[i] = 0.f; }
    }

    // plane z0
    load_plane(P, T, z0, h0, w0, tid, sp);
    __syncthreads();
    compute_A(sp, hy, wg, ss_0, ds_0, sd_0);

    float acc = 0.0f;

    for (int zo = z0; zo < z0 + ZC; ++zo) {
        const int zp = zo + 1;
        if (zp < D_DIM) {
            __syncthreads();                 // protect prior compute_A reads
            load_plane(P, T, zp, h0, w0, tid, sp);
            __syncthreads();
            compute_A(sp, hy, wg, ss_p1, ds_p1, sd_p1);
        } else {
#pragma unroll
            for (int i = 0; i < WPT; ++i) { ss_p1[i] = 0.f; ds_p1[i] = 0.f; sd_p1[i] = 0.f; }
        }

#pragma unroll
        for (int i = 0; i < WPT; ++i) {
            float gd = ss_p1[i] - ss_m1[i];                       // d/dz
            float gh = ds_m1[i] + 2.0f * ds_0[i] + ds_p1[i];      // d/dh
            float gw = sd_m1[i] + 2.0f * sd_0[i] + sd_p1[i];      // d/dw
            acc += fabsf(gd) + fabsf(gh) + fabsf(gw);
        }

#pragma unroll
        for (int i = 0; i < WPT; ++i) {
            ss_m1[i] = ss_0[i];  ds_m1[i] = ds_0[i];  sd_m1[i] = sd_0[i];
            ss_0[i]  = ss_p1[i]; ds_0[i]  = ds_p1[i]; sd_0[i]  = sd_p1[i];
        }
    }

    // block reduction
#pragma unroll
    for (int off = 16; off > 0; off >>= 1)
        acc += __shfl_down_sync(0xffffffffu, acc, off);

    __shared__ float wsum[8];
    const int lane = tid & 31;
    const int warp = tid >> 5;
    if (lane == 0) wsum[warp] = acc;
    __syncthreads();
    if (warp == 0) {
        float v = (lane < 8) ? wsum[lane] : 0.0f;
#pragma unroll
        for (int off = 4; off > 0; off >>= 1)
            v += __shfl_down_sync(0xffffffffu, v, off);
        if (lane == 0) atomicAdd(out, v * kINV_N());
    }
}

extern "C" void kernel_launch(void* const* d_in, const int* in_sizes, int n_in,
                              void* d_out, int out_size) {
    const float* pred = (const float*)d_in[0];
    const float* tgt  = (const float*)d_in[1];
    float* out = (float*)d_out;

    sg3d_zero_out<<<1, 1>>>(out);

    dim3 grid(W_DIM / TW, H_DIM / TH, BC_DIM * (D_DIM / ZC));  // 4 x 4 x 32
    dim3 block(8, 32);                                          // 256 threads
    sg3d_loss_kernel<<<grid, block>>>(pred, tgt, out);
}

// round 2
// speedup vs baseline: 3.7558x; 3.7558x over previous
#include <cuda_runtime.h>

// SpatialGradientLoss3D: mean |sobel3d(pred) - sobel3d(target)| over 3 axes.
// Linear conv => sobel of e = pred - target directly. Separable kernels:
// per-plane partials ss/ds/sd in registers, 3-deep z rotation.
// Shapes fixed: (B=4, C=4, D=64, H=128, W=128), fp32, out = 1 float.
//
// R2: software-pipelined z-march. Double-buffered smem planes; next plane's
// LDGs issued into registers while current plane is computed. One
// __syncthreads per iteration. ZC=16 -> 1024 blocks. Index math hoisted.

#define D_DIM 64
#define H_DIM 128
#define W_DIM 128
#define HW    (H_DIM * W_DIM)
#define BC_DIM 16
#define TW 32
#define TH 32
#define ZC 16
#define WPT 4
#define STRIDE 35            // conflict-free: (hy*35 + wg*4 + i) mod 32 bijective over warp
#define PLANE_ROWS 34
#define PLANE_COLS 34
#define PLANE_ELEMS (PLANE_ROWS * PLANE_COLS)   // 1156
#define NSLOT 5

__device__ __forceinline__ float kINV_N() {
    return 1.0f / (3.0f * 16.0f * 64.0f * 128.0f * 128.0f);
}

__global__ void sg3d_zero_out(float* out) { out[0] = 0.0f; }

// Issue global loads for plane z into registers (no smem, no sync).
__device__ __forceinline__ void issue_loads(const float* __restrict__ P,
                                            const float* __restrict__ T,
                                            int z, const int* soff,
                                            unsigned vmask,
                                            float* vP, float* vT) {
    const int zb = z * HW;
#pragma unroll
    for (int k = 0; k < NSLOT; ++k) {
        vP[k] = 0.0f; vT[k] = 0.0f;
        if (vmask & (1u << k)) {
            vP[k] = __ldg(P + zb + soff[k]);
            vT[k] = __ldg(T + zb + soff[k]);
        }
    }
}

// Store register-held plane (diff) into smem buffer.
__device__ __forceinline__ void store_plane(float* sp, const float* vP, const float* vT,
                                            const int* sidx, unsigned rmask) {
#pragma unroll
    for (int k = 0; k < NSLOT; ++k)
        if (rmask & (1u << k))
            sp[sidx[k]] = vP[k] - vT[k];
}

// Separable (w then h) per-plane partials for this thread's 4 output cols.
__device__ __forceinline__ void compute_A(const float* sp, int hy, int wg,
                                          float* ss, float* ds, float* sd) {
    float rs[3][6];
#pragma unroll
    for (int rr = 0; rr < 3; ++rr) {
        const float* row = sp + (hy + rr) * STRIDE + wg * WPT;
#pragma unroll
        for (int i = 0; i < 6; ++i) rs[rr][i] = row[i];
    }
#pragma unroll
    for (int i = 0; i < WPT; ++i) {
        float as_m = rs[0][i] + 2.0f * rs[0][i + 1] + rs[0][i + 2];
        float as_0 = rs[1][i] + 2.0f * rs[1][i + 1] + rs[1][i + 2];
        float as_p = rs[2][i] + 2.0f * rs[2][i + 1] + rs[2][i + 2];
        float ad_m = rs[0][i + 2] - rs[0][i];
        float ad_0 = rs[1][i + 2] - rs[1][i];
        float ad_p = rs[2][i + 2] - rs[2][i];
        ss[i] = as_m + 2.0f * as_0 + as_p;
        ds[i] = as_p - as_m;
        sd[i] = ad_m + 2.0f * ad_0 + ad_p;
    }
}

__global__ __launch_bounds__(256, 3)
void sg3d_loss_kernel(const float* __restrict__ pred,
                      const float* __restrict__ tgt,
                      float* __restrict__ out) {
    const int wg = threadIdx.x;   // 0..7
    const int hy = threadIdx.y;   // 0..31
    const int tid = hy * 8 + wg;

    const int w0 = blockIdx.x * TW;
    const int h0 = blockIdx.y * TH;
    const int bc = blockIdx.z >> 2;           // 16 bc values
    const int z0 = (blockIdx.z & 3) * ZC;     // 4 z-chunks

    const size_t base = (size_t)bc * D_DIM * HW;
    const float* P = pred + base;
    const float* T = tgt + base;

    __shared__ float sp[2][PLANE_ROWS * STRIDE];

    // ---- hoisted per-slot index math ----
    int soff[NSLOT], sidx[NSLOT];
    unsigned rmask = 0, vmask = 0;
#pragma unroll
    for (int k = 0; k < NSLOT; ++k) {
        int idx = tid + k * 256;
        soff[k] = 0; sidx[k] = 0;
        if (idx < PLANE_ELEMS) {
            rmask |= (1u << k);
            int r = idx / PLANE_COLS;
            int c = idx - r * PLANE_COLS;
            sidx[k] = r * STRIDE + c;
            int gh = h0 - 1 + r;
            int gw = w0 - 1 + c;
            if ((unsigned)gh < (unsigned)H_DIM && (unsigned)gw < (unsigned)W_DIM) {
                vmask |= (1u << k);
                soff[k] = gh * W_DIM + gw;
            }
        }
    }

    float vP[NSLOT], vT[NSLOT];
    float ss_m1[WPT], ds_m1[WPT], sd_m1[WPT];
    float ss_0[WPT],  ds_0[WPT],  sd_0[WPT];
    float ss_p1[WPT], ds_p1[WPT], sd_p1[WPT];

    // ---- prologue: planes z0-1 (buf0) and z0 (buf1), prefetch z0+1 ----
    if (z0 > 0) {
        issue_loads(P, T, z0 - 1, soff, vmask, vP, vT);
    } else {
#pragma unroll
        for (int k = 0; k < NSLOT; ++k) { vP[k] = 0.f; vT[k] = 0.f; }
    }
    store_plane(sp[0], vP, vT, sidx, rmask);
    issue_loads(P, T, z0, soff, vmask, vP, vT);          // overlap with sync+compute
    __syncthreads();
    compute_A(sp[0], hy, wg, ss_m1, ds_m1, sd_m1);

    store_plane(sp[1], vP, vT, sidx, rmask);
    issue_loads(P, T, z0 + 1, soff, vmask, vP, vT);      // z0+1 <= 49+... always < D here (z0<=48)
    __syncthreads();
    compute_A(sp[1], hy, wg, ss_0, ds_0, sd_0);

    float acc = 0.0f;
    int buf = 0;

    // ---- steady state: one sync per z-plane ----
    for (int zo = z0; zo < z0 + ZC; ++zo) {
        const int zp = zo + 1;
        if (zp < D_DIM) {
            store_plane(sp[buf], vP, vT, sidx, rmask);   // regs hold plane zp
            const int zn = zp + 1;
            if (zn <= z0 + ZC && zn < D_DIM) {
                issue_loads(P, T, zn, soff, vmask, vP, vT);  // prefetch next
            }
            __syncthreads();
            compute_A(sp[buf], hy, wg, ss_p1, ds_p1, sd_p1);
            buf ^= 1;
        } else {
#pragma unroll
            for (int i = 0; i < WPT; ++i) { ss_p1[i] = 0.f; ds_p1[i] = 0.f; sd_p1[i] = 0.f; }
        }

#pragma unroll
        for (int i = 0; i < WPT; ++i) {
            float gd = ss_p1[i] - ss_m1[i];
            float gh = ds_m1[i] + 2.0f * ds_0[i] + ds_p1[i];
            float gw = sd_m1[i] + 2.0f * sd_0[i] + sd_p1[i];
            acc += fabsf(gd) + fabsf(gh) + fabsf(gw);
        }
#pragma unroll
        for (int i = 0; i < WPT; ++i) {
            ss_m1[i] = ss_0[i];  ds_m1[i] = ds_0[i];  sd_m1[i] = sd_0[i];
            ss_0[i]  = ss_p1[i]; ds_0[i]  = ds_p1[i]; sd_0[i]  = sd_p1[i];
        }
    }

    // ---- reduction ----
#pragma unroll
    for (int off = 16; off > 0; off >>= 1)
        acc += __shfl_down_sync(0xffffffffu, acc, off);

    __shared__ float wsum[8];
    const int lane = tid & 31;
    const int warp = tid >> 5;
    if (lane == 0) wsum[warp] = acc;
    __syncthreads();
    if (warp == 0) {
        float v = (lane < 8) ? wsum[lane] : 0.0f;
#pragma unroll
        for (int off = 4; off > 0; off >>= 1)
            v += __shfl_down_sync(0xffffffffu, v, off);
        if (lane == 0) atomicAdd(out, v * kINV_N());
    }
}

extern "C" void kernel_launch(void* const* d_in, const int* in_sizes, int n_in,
                              void* d_out, int out_size) {
    const float* pred = (const float*)d_in[0];
    const float* tgt  = (const float*)d_in[1];
    float* out = (float*)d_out;

    sg3d_zero_out<<<1, 1>>>(out);

    dim3 grid(W_DIM / TW, H_DIM / TH, BC_DIM * (D_DIM / ZC));  // 4 x 4 x 64 = 1024
    dim3 block(8, 32);
    sg3d_loss_kernel<<<grid, block>>>(pred, tgt, out);
}